// round 3
// baseline (speedup 1.0000x reference)
#include <cuda_runtime.h>
#include <cuda_bf16.h>

#define N_NODES 100000
#define N_EDGES 1600000

// ---------------- static scratch (no allocations allowed) ----------------
__device__ int   g_deg[N_NODES];
__device__ int   g_cursor[N_NODES];
__device__ int   g_rowptr[N_NODES + 1];
__device__ int   g_csr[N_EDGES];
__device__ __align__(16) float g_hbuf[(size_t)N_NODES * 64];
__device__ float g_pool[64];

// ---------------- K0: zero counters ----------------
__global__ void k_zero() {
    int i = blockIdx.x * blockDim.x + threadIdx.x;
    int stride = gridDim.x * blockDim.x;
    for (int t = i; t < N_NODES; t += stride) { g_deg[t] = 0; g_cursor[t] = 0; }
    if (i < 64) g_pool[i] = 0.f;
}

// ---------------- K1: degree histogram ----------------
__global__ void k_hist(const int* __restrict__ dst) {
    int i = blockIdx.x * blockDim.x + threadIdx.x;
    int stride = gridDim.x * blockDim.x;
    for (int e = i; e < N_EDGES; e += stride) atomicAdd(&g_deg[dst[e]], 1);
}

// ---------------- K2: exclusive scan (single block, 1024 threads) ----------------
__global__ void k_scan() {
    __shared__ int s[1024];
    int t = threadIdx.x;
    const int chunk = (N_NODES + 1023) / 1024;  // 98
    int start = t * chunk;
    int end = min(start + chunk, N_NODES);
    int sum = 0;
    for (int i = start; i < end; i++) sum += g_deg[i];
    s[t] = sum;
    __syncthreads();
    for (int off = 1; off < 1024; off <<= 1) {
        int v = (t >= off) ? s[t - off] : 0;
        __syncthreads();
        s[t] += v;
        __syncthreads();
    }
    int base = s[t] - sum;  // exclusive prefix for this chunk
    for (int i = start; i < end; i++) { g_rowptr[i] = base; base += g_deg[i]; }
    if (t == 1023) g_rowptr[N_NODES] = s[1023];
}

// ---------------- K3: fill CSR buckets ----------------
__global__ void k_fill(const int* __restrict__ src, const int* __restrict__ dst) {
    int i = blockIdx.x * blockDim.x + threadIdx.x;
    int stride = gridDim.x * blockDim.x;
    for (int e = i; e < N_EDGES; e += stride) {
        int d = dst[e];
        int p = atomicAdd(&g_cursor[d], 1);
        g_csr[g_rowptr[d] + p] = src[e];
    }
}

// ---------------- K4: fused GINConv1 (gather 128ch + MLP 128->32->64, relu) ------
// One warp per node. Shared per warp: [0..127] h0, [128..159] h1.
__global__ void __launch_bounds__(256) k_layer1(
    const float4* __restrict__ x4,
    const float* __restrict__ W1, const float* __restrict__ b1,
    const float* __restrict__ W2, const float* __restrict__ b2)
{
    __shared__ float sh[8 * 160];
    int gw = (blockIdx.x * blockDim.x + threadIdx.x) >> 5;
    int lane = threadIdx.x & 31;
    float* s0 = sh + (threadIdx.x >> 5) * 160;
    if (gw >= N_NODES) return;

    // (1+eps)*x_i + sum_{j->i} x_j   (eps=0)
    float4 acc = x4[(size_t)gw * 32 + lane];
    int beg = g_rowptr[gw], end = g_rowptr[gw + 1];
    for (int e = beg; e < end; e++) {
        int j = g_csr[e];
        float4 v = x4[(size_t)j * 32 + lane];
        acc.x += v.x; acc.y += v.y; acc.z += v.z; acc.w += v.w;
    }
    *reinterpret_cast<float4*>(s0 + lane * 4) = acc;
    __syncwarp();

    // MLP layer A: 128 -> 32, relu. Lane computes output channel = lane.
    float o1 = b1[lane];
#pragma unroll 16
    for (int k = 0; k < 128; k++) o1 = fmaf(s0[k], W1[k * 32 + lane], o1);
    o1 = fmaxf(o1, 0.f);
    s0[128 + lane] = o1;
    __syncwarp();

    // MLP layer B: 32 -> 64 (plain), then outer relu. Lane computes c=lane, c=lane+32.
    float oa = b2[lane], ob = b2[32 + lane];
#pragma unroll
    for (int k = 0; k < 32; k++) {
        float h = s0[128 + k];
        oa = fmaf(h, W2[k * 64 + lane], oa);
        ob = fmaf(h, W2[k * 64 + 32 + lane], ob);
    }
    oa = fmaxf(oa, 0.f);
    ob = fmaxf(ob, 0.f);
    g_hbuf[(size_t)gw * 64 + lane] = oa;
    g_hbuf[(size_t)gw * 64 + 32 + lane] = ob;
}

// ---------------- K5: fused GINConv2 (gather 64ch + MLP 64->64->64, relu) --------
// One warp per node. Shared per warp: [0..63] g0, [64..127] g1.
__global__ void __launch_bounds__(256) k_layer2(
    const float* __restrict__ W3, const float* __restrict__ b3,
    const float* __restrict__ W4, const float* __restrict__ b4,
    float* __restrict__ out)
{
    __shared__ float sh[8 * 128];
    int gw = (blockIdx.x * blockDim.x + threadIdx.x) >> 5;
    int lane = threadIdx.x & 31;
    float* s0 = sh + (threadIdx.x >> 5) * 128;
    if (gw >= N_NODES) return;

    const float2* h2 = reinterpret_cast<const float2*>(g_hbuf);
    float2 acc = h2[(size_t)gw * 32 + lane];
    int beg = g_rowptr[gw], end = g_rowptr[gw + 1];
    for (int e = beg; e < end; e++) {
        int j = g_csr[e];
        float2 v = h2[(size_t)j * 32 + lane];
        acc.x += v.x; acc.y += v.y;
    }
    *reinterpret_cast<float2*>(s0 + lane * 2) = acc;
    __syncwarp();

    // MLP layer A: 64 -> 64, relu
    float oa = b3[lane], ob = b3[32 + lane];
#pragma unroll 8
    for (int k = 0; k < 64; k++) {
        float g = s0[k];
        oa = fmaf(g, W3[k * 64 + lane], oa);
        ob = fmaf(g, W3[k * 64 + 32 + lane], ob);
    }
    oa = fmaxf(oa, 0.f);
    ob = fmaxf(ob, 0.f);
    s0[64 + lane] = oa;
    s0[96 + lane] = ob;
    __syncwarp();

    // MLP layer B: 64 -> 64 (plain), then outer relu
    float oc = b4[lane], od = b4[32 + lane];
#pragma unroll 8
    for (int k = 0; k < 64; k++) {
        float g = s0[64 + k];
        oc = fmaf(g, W4[k * 64 + lane], oc);
        od = fmaf(g, W4[k * 64 + 32 + lane], od);
    }
    oc = fmaxf(oc, 0.f);
    od = fmaxf(od, 0.f);
    out[(size_t)gw * 64 + lane] = oc;
    out[(size_t)gw * 64 + 32 + lane] = od;
}

// ---------------- K6: pooled partial reduction ----------------
// 256 threads/block: thread handles channel t&63; 4 threads (t>>6) stride rows.
__global__ void k_pool(const float* __restrict__ out) {
    int c = threadIdx.x & 63;
    int s = threadIdx.x >> 6;  // 0..3
    int rows_per_block = (N_NODES + gridDim.x - 1) / gridDim.x;
    int r0 = blockIdx.x * rows_per_block;
    int r1 = min(r0 + rows_per_block, N_NODES);
    float acc = 0.f;
    for (int r = r0 + s; r < r1; r += 4) acc += out[(size_t)r * 64 + c];
    __shared__ float sp[256];
    sp[threadIdx.x] = acc;
    __syncthreads();
    if (s == 0) {
        float v = sp[c] + sp[64 + c] + sp[128 + c] + sp[192 + c];
        atomicAdd(&g_pool[c], v);
    }
}

// ---------------- K7: finalize pooled mean ----------------
__global__ void k_poolfin(float* __restrict__ out, int off) {
    int t = threadIdx.x;
    if (t < 64) out[off + t] = g_pool[t] * (1.0f / N_NODES);
}

// ---------------- launch ----------------
extern "C" void kernel_launch(void* const* d_in, const int* in_sizes, int n_in,
                              void* d_out, int out_size) {
    const float* x  = (const float*)d_in[0];
    const int*   ei = (const int*)d_in[1];
    // d_in[2] = batch (unused: reference overwrites with zeros -> single graph)
    const float* W1 = (const float*)d_in[3];
    const float* b1 = (const float*)d_in[4];
    const float* W2 = (const float*)d_in[5];
    const float* b2 = (const float*)d_in[6];
    const float* W3 = (const float*)d_in[7];
    const float* b3 = (const float*)d_in[8];
    const float* W4 = (const float*)d_in[9];
    const float* b4 = (const float*)d_in[10];
    float* out = (float*)d_out;

    const int* src = ei;            // edge_index[0, :]
    const int* dst = ei + N_EDGES;  // edge_index[1, :]
    int h_off = out_size - 64;      // pooled goes at the tail

    k_zero<<<256, 256>>>();
    k_hist<<<512, 256>>>(dst);
    k_scan<<<1, 1024>>>();
    k_fill<<<512, 256>>>(src, dst);

    int blocks = (N_NODES * 32 + 255) / 256;  // 12500, one warp per node
    k_layer1<<<blocks, 256>>>((const float4*)x, W1, b1, W2, b2);
    k_layer2<<<blocks, 256>>>(W3, b3, W4, b4, out);

    k_pool<<<128, 256>>>(out);
    k_poolfin<<<1, 64>>>(out, h_off);
}